// round 14
// baseline (speedup 1.0000x reference)
#include <cuda_runtime.h>
#include <cuda_fp16.h>
#include <cstdint>

// Problem constants
#define BB 16
#define LL 2048
#define DD 512
#define HH 8
#define DHH 64
#define FF 2048
#define NLAYERS 4
#define VV 21
#define MM (BB * LL)       // 32768
#define NQKV 1536

// ---------------------------------------------------------------------------
// Scratch (device globals; no runtime allocation)
// ---------------------------------------------------------------------------
__device__ __align__(256) __half g_hin[MM * DD];     // residual stream (fp16)
__device__ __align__(256) __half g_qkv[MM * NQKV];
__device__ __align__(256) __half g_tmp[MM * DD];
__device__ __align__(256) __half g_tmp2[MM * DD];
__device__ __align__(256) __half g_att[MM * DD];
__device__ __align__(256) __half g_ff[MM * FF];
// transposed fp16 weights [N][K] per layer: Wqkv[1536x512], Wo[512x512], W1[2048x512], W2[512x2048]
#define WPL 3145728
#define W_QKV 0
#define W_O   786432
#define W_1   1048576
#define W_2   2097152
__device__ __align__(256) __half g_w[NLAYERS * WPL];
__device__ __align__(256) float g_bqkv[NLAYERS * NQKV];

// ---------------------------------------------------------------------------
// PTX helpers (generic sm_80+: cp.async, ldmatrix, mma.sync)
// ---------------------------------------------------------------------------
__device__ __forceinline__ uint32_t smem_u32(const void* p) {
    uint32_t a;
    asm("{ .reg .u64 t; cvta.to.shared.u64 t, %1; cvt.u32.u64 %0, t; }" : "=r"(a) : "l"(p));
    return a;
}
__device__ __forceinline__ void cp_async16(uint32_t saddr, const void* gaddr) {
    asm volatile("cp.async.cg.shared.global [%0], [%1], 16;" :: "r"(saddr), "l"(gaddr));
}
#define CP_COMMIT() asm volatile("cp.async.commit_group;" ::: "memory")
#define CP_WAIT1()  asm volatile("cp.async.wait_group 1;" ::: "memory")

__device__ __forceinline__ void ldsm_x4(uint32_t addr, uint32_t& r0, uint32_t& r1, uint32_t& r2, uint32_t& r3) {
    asm volatile("ldmatrix.sync.aligned.m8n8.x4.shared.b16 {%0,%1,%2,%3}, [%4];"
                 : "=r"(r0), "=r"(r1), "=r"(r2), "=r"(r3) : "r"(addr));
}
__device__ __forceinline__ void mma16816(float* c, const uint32_t* a, uint32_t b0, uint32_t b1) {
    asm volatile("mma.sync.aligned.m16n8k16.row.col.f32.f16.f16.f32 "
                 "{%0,%1,%2,%3}, {%4,%5,%6,%7}, {%8,%9}, {%0,%1,%2,%3};"
                 : "+f"(c[0]), "+f"(c[1]), "+f"(c[2]), "+f"(c[3])
                 : "r"(a[0]), "r"(a[1]), "r"(a[2]), "r"(a[3]), "r"(b0), "r"(b1));
}

// dot-accumulate 8 halves (one uint4) of a and b into acc (fp32)
__device__ __forceinline__ void dot8(float& acc, uint4 a, uint4 b) {
    const __half2* ah = (const __half2*)&a;
    const __half2* bh = (const __half2*)&b;
    #pragma unroll
    for (int i = 0; i < 4; ++i) {
        float2 af = __half22float2(ah[i]);
        float2 bf = __half22float2(bh[i]);
        acc += af.x * bf.x + af.y * bf.y;
    }
}

// ---------------------------------------------------------------------------
// Fused weight preprocess: ONE kernel transposes all 24 matrices to [N][K] fp16.
// ---------------------------------------------------------------------------
__global__ __launch_bounds__(256) void prep_weights(
    const float* __restrict__ Wq, const float* __restrict__ Wk,
    const float* __restrict__ Wv, const float* __restrict__ Wo,
    const float* __restrict__ W1, const float* __restrict__ W2,
    __half* __restrict__ w)
{
    __shared__ float tile[32][33];
    int b = blockIdx.x;
    int layer = b / 3072, r = b % 3072;
    size_t lw = (size_t)layer * WPL;
    const float* in; __half* o; int K, N, t;
    if (r < 256)       { in = Wq + (size_t)layer * 262144;  o = w + lw + W_QKV;           K = 512;  N = 512;  t = r; }
    else if (r < 512)  { in = Wk + (size_t)layer * 262144;  o = w + lw + W_QKV + 262144;  K = 512;  N = 512;  t = r - 256; }
    else if (r < 768)  { in = Wv + (size_t)layer * 262144;  o = w + lw + W_QKV + 524288;  K = 512;  N = 512;  t = r - 512; }
    else if (r < 1024) { in = Wo + (size_t)layer * 262144;  o = w + lw + W_O;             K = 512;  N = 512;  t = r - 768; }
    else if (r < 2048) { in = W1 + (size_t)layer * 1048576; o = w + lw + W_1;             K = 512;  N = 2048; t = r - 1024; }
    else               { in = W2 + (size_t)layer * 1048576; o = w + lw + W_2;             K = 2048; N = 512;  t = r - 2048; }

    int ntn = N / 32;
    int n0 = (t % ntn) * 32, k0 = (t / ntn) * 32;
    int tx = threadIdx.x & 31, ty = threadIdx.x >> 5;   // ty 0..7
    #pragma unroll
    for (int i = 0; i < 4; ++i) {
        int k = k0 + ty + i * 8;
        tile[ty + i * 8][tx] = in[(size_t)k * N + n0 + tx];
    }
    __syncthreads();
    #pragma unroll
    for (int i = 0; i < 4; ++i) {
        int n = n0 + ty + i * 8;
        o[(size_t)n * K + k0 + tx] = __float2half_rn(tile[tx][ty + i * 8]);
    }
}

// All layers' QKV biases in one kernel
__global__ __launch_bounds__(256) void prep_bias(
    const float* __restrict__ bq, const float* __restrict__ bk,
    const float* __restrict__ bv, float* __restrict__ out)
{
    int i = blockIdx.x * 256 + threadIdx.x;   // over NLAYERS*1536
    int layer = i / NQKV, j = i - layer * NQKV;
    float v = (j < 512) ? bq[layer * 512 + j]
            : (j < 1024 ? bk[layer * 512 + j - 512] : bv[layer * 512 + j - 1024]);
    out[i] = v;
}

// ---------------------------------------------------------------------------
// Embedding: h16 = (half)(tok[x] + pos)
// ---------------------------------------------------------------------------
__global__ __launch_bounds__(256) void embed_kernel(
    const int* __restrict__ x, const float* __restrict__ tok,
    const float* __restrict__ pos, __half* __restrict__ oh)
{
    int i = blockIdx.x * blockDim.x + threadIdx.x;   // over MM*DD/4
    int bl = i >> 7;
    int d4 = (i & 127) << 2;
    int l  = bl & (LL - 1);
    int t  = x[bl];
    float4 te = *(const float4*)&tok[t * DD + d4];
    float4 pe = *(const float4*)&pos[l * DD + d4];
    size_t base = (size_t)bl * DD + d4;
    __half2 p0; p0.x = __float2half_rn(te.x + pe.x); p0.y = __float2half_rn(te.y + pe.y);
    __half2 p1; p1.x = __float2half_rn(te.z + pe.z); p1.y = __float2half_rn(te.w + pe.w);
    *(__half2*)&oh[base] = p0; *(__half2*)&oh[base + 2] = p1;
}

// ---------------------------------------------------------------------------
// Tensor-core GEMM:  C[M,N] = A[M,Kstride](fp16 rm) @ W[N,Kstride](fp16) + bias
// BM=128, BN=128, BK=64, 256 threads / 8 warps, warp tile 64x32 (grid 2Mx4N),
// 2-stage cp.async pipeline, 144B-padded rows. Hot loop unchanged from R9/R10
// (at the sm_100 legacy mma.sync floor, ~278 TF/s).
// Split-K linearized into blockIdx.x (2D grid): gridDim.x = (N/BN)*nsplit.
// z = blockIdx.x / (N/BN) selects K-chunk [z*Kiter, ...); z=0 -> out0 (+bias),
// z=1 -> out1 (no bias). Normal GEMMs: gridDim.x = N/BN, Kiter = Kstride.
// ---------------------------------------------------------------------------
#define BM 128
#define BN 128
#define BK 64
#define PAD_STRIDE 144           // 128B row + 16B pad
#define TILE_BYTES 18432         // 128 * 144
#define STAGE_BYTES 36864
#define SMEM_GEMM (2 * STAGE_BYTES)

__global__ __launch_bounds__(256, 2) void gemm_tc(
    const __half* __restrict__ A, const __half* __restrict__ B,
    const float* __restrict__ bias,
    __half* __restrict__ out0, __half* __restrict__ out1,
    int M, int N, int Kstride, int Kiter, int relu)
{
    extern __shared__ char smem[];
    const uint32_t sb = smem_u32(smem);
    const int tid = threadIdx.x, wid = tid >> 5, lane = tid & 31;
    const int warpM = wid >> 2, warpN = wid & 3;       // 2 x 4 warp grid

    const int ncb = N / BN;                            // column blocks
    const int zIdx = blockIdx.x / ncb;                 // K-split index (0 or 1)
    const int colB = blockIdx.x - zIdx * ncb;

    const int rowBase = blockIdx.y * BM;
    const int nBase = colB * BN;
    const int kOff = zIdx * Kiter;
    __half* outH = zIdx ? out1 : out0;
    const int addBias = (zIdx == 0);

    auto load_stage = [&](int stage, int kc) {
        uint32_t st = sb + (uint32_t)(stage & 1) * STAGE_BYTES;
        #pragma unroll
        for (int i = 0; i < 4; ++i) {
            int c = tid + i * 256;            // chunk id 0..1023
            int row = c >> 3;
            int kch = c & 7;                   // 16B chunk within 128B row
            uint32_t so = st + row * PAD_STRIDE + kch * 16;
            cp_async16(so, A + (size_t)(rowBase + row) * Kstride + kOff + kc + kch * 8);
            cp_async16(so + TILE_BYTES, B + (size_t)(nBase + row) * Kstride + kOff + kc + kch * 8);
        }
        CP_COMMIT();
    };

    float acc[4][4][4];
    #pragma unroll
    for (int mi = 0; mi < 4; ++mi)
        #pragma unroll
        for (int ni = 0; ni < 4; ++ni)
            #pragma unroll
            for (int j = 0; j < 4; ++j) acc[mi][ni][j] = 0.0f;

    const int S = Kiter / BK;
    load_stage(0, 0);
    load_stage(1, BK);

    const int r8 = lane & 7, mt = lane >> 3;
    uint32_t aOff[4], bOff[2];
    #pragma unroll
    for (int mi = 0; mi < 4; ++mi)
        aOff[mi] = (uint32_t)((warpM * 64 + mi * 16 + (mt & 1) * 8 + r8) * PAD_STRIDE + ((mt >> 1) * 8) * 2);
    #pragma unroll
    for (int g = 0; g < 2; ++g)
        bOff[g] = (uint32_t)(TILE_BYTES + (warpN * 32 + g * 16 + (mt >> 1) * 8 + r8) * PAD_STRIDE + ((mt & 1) * 8) * 2);

    for (int it = 0; it < S; ++it) {
        CP_WAIT1();                 // stage it resident (stage it+1 may be in flight)
        __syncthreads();

        uint32_t st = sb + (uint32_t)(it & 1) * STAGE_BYTES;
        #pragma unroll
        for (int ks = 0; ks < 4; ++ks) {      // 4 x K16 per BK=64
            uint32_t af[4][4], bf[2][4];
            #pragma unroll
            for (int g = 0; g < 2; ++g)
                ldsm_x4(st + bOff[g] + ks * 32, bf[g][0], bf[g][1], bf[g][2], bf[g][3]);
            #pragma unroll
            for (int mi = 0; mi < 4; ++mi)
                ldsm_x4(st + aOff[mi] + ks * 32, af[mi][0], af[mi][1], af[mi][2], af[mi][3]);
            #pragma unroll
            for (int mi = 0; mi < 4; ++mi)
                #pragma unroll
                for (int g = 0; g < 2; ++g) {
                    mma16816(acc[mi][2 * g],     af[mi], bf[g][0], bf[g][1]);
                    mma16816(acc[mi][2 * g + 1], af[mi], bf[g][2], bf[g][3]);
                }
        }
        __syncthreads();            // all warps done reading buffer it&1
        if (it + 2 < S) load_stage(it + 2, (it + 2) * BK);
        else CP_COMMIT();           // keep group count consistent
    }

    // epilogue: fp16 out (+optional relu); bias only on z==0
    const int mrow0 = rowBase + warpM * 64 + (lane >> 2);
    const int ncol0 = nBase + warpN * 32 + (lane & 3) * 2;
    #pragma unroll
    for (int mi = 0; mi < 4; ++mi) {
        #pragma unroll
        for (int ni = 0; ni < 4; ++ni) {
            int n = ncol0 + ni * 8;
            float b0 = addBias ? bias[n] : 0.0f;
            float b1 = addBias ? bias[n + 1] : 0.0f;
            int m0 = mrow0 + mi * 16;
            float v00 = acc[mi][ni][0] + b0, v01 = acc[mi][ni][1] + b1;
            float v10 = acc[mi][ni][2] + b0, v11 = acc[mi][ni][3] + b1;
            if (relu) {
                v00 = fmaxf(v00, 0.0f); v01 = fmaxf(v01, 0.0f);
                v10 = fmaxf(v10, 0.0f); v11 = fmaxf(v11, 0.0f);
            }
            __half2 h0, h1;
            h0.x = __float2half_rn(v00); h0.y = __float2half_rn(v01);
            h1.x = __float2half_rn(v10); h1.y = __float2half_rn(v11);
            *(__half2*)&outH[(size_t)m0 * N + n] = h0;
            *(__half2*)&outH[(size_t)(m0 + 8) * N + n] = h1;
        }
    }
}

// ---------------------------------------------------------------------------
// Tree attention: ONE WARP per token (b,l), all 8 heads, 16B loads.
// ---------------------------------------------------------------------------
__global__ __launch_bounds__(256) void tree_attn(
    const __half* __restrict__ qkv, const int* __restrict__ parents,
    __half* __restrict__ oh)
{
    int bl = blockIdx.x * 8 + (threadIdx.x >> 5);
    int lane = threadIdx.x & 31;
    int l = bl & (LL - 1);

    int p = parents[l];
    int pk = (p >= 0) ? (p + 1) : l;
    int pbl = (bl - l) + pk;

    size_t rb  = (size_t)bl  * NQKV + lane * 16;
    size_t prb = (size_t)pbl * NQKV + lane * 16;

    uint4 q0  = *(const uint4*)(qkv + rb);
    uint4 q1  = *(const uint4*)(qkv + rb + 8);
    uint4 k0  = *(const uint4*)(qkv + rb + 512);
    uint4 k1  = *(const uint4*)(qkv + rb + 520);
    uint4 kp0 = *(const uint4*)(qkv + prb + 512);
    uint4 kp1 = *(const uint4*)(qkv + prb + 520);

    float d0 = 0.0f, d1 = 0.0f;
    dot8(d0, q0, k0);  dot8(d0, q1, k1);
    dot8(d1, q0, kp0); dot8(d1, q1, kp1);

    // reduce within 4-lane head group
    #pragma unroll
    for (int off = 1; off < 4; off <<= 1) {
        d0 += __shfl_xor_sync(0xffffffffu, d0, off);
        d1 += __shfl_xor_sync(0xffffffffu, d1, off);
    }

    const float scale = 0.125f;   // 1/sqrt(64)
    float s0 = d0 * scale;
    float s1 = (p >= 0) ? d1 * scale : -1e9f;
    float m  = fmaxf(s0, s1);
    float e0 = __expf(s0 - m);
    float e1 = __expf(s1 - m);
    float inv = 1.0f / (e0 + e1);
    float a0 = e0 * inv, a1 = e1 * inv;

    uint4 v0  = *(const uint4*)(qkv + rb + 1024);
    uint4 v1  = *(const uint4*)(qkv + rb + 1032);
    uint4 vp0 = *(const uint4*)(qkv + prb + 1024);
    uint4 vp1 = *(const uint4*)(qkv + prb + 1032);

    uint4 o0, o1;
    {
        const __half2* vs = (const __half2*)&v0;
        const __half2* vp = (const __half2*)&vp0;
        __half2* oo = (__half2*)&o0;
        #pragma unroll
        for (int i = 0; i < 4; ++i) {
            float2 a = __half22float2(vs[i]);
            float2 b = __half22float2(vp[i]);
            __half2 r;
            r.x = __float2half_rn(a0 * a.x + a1 * b.x);
            r.y = __float2half_rn(a0 * a.y + a1 * b.y);
            oo[i] = r;
        }
        const __half2* vs1 = (const __half2*)&v1;
        const __half2* vp1h = (const __half2*)&vp1;
        __half2* oo1 = (__half2*)&o1;
        #pragma unroll
        for (int i = 0; i < 4; ++i) {
            float2 a = __half22float2(vs1[i]);
            float2 b = __half22float2(vp1h[i]);
            __half2 r;
            r.x = __float2half_rn(a0 * a.x + a1 * b.x);
            r.y = __float2half_rn(a0 * a.y + a1 * b.y);
            oo1[i] = r;
        }
    }

    size_t ob = (size_t)bl * DD + lane * 16;
    *(uint4*)(oh + ob)     = o0;
    *(uint4*)(oh + ob + 8) = o1;
}

// ---------------------------------------------------------------------------
// Fused residual-add + LayerNorm: ONE WARP per row, shfl-only, 16B loads.
// nres = 1: x = h + r1 ;  nres = 2: x = h + r1 + r2
// ---------------------------------------------------------------------------
template <int NRES>
__global__ __launch_bounds__(256) void add_ln(
    __half* __restrict__ h, const __half* __restrict__ r1,
    const __half* __restrict__ r2,
    const float* __restrict__ gamma, const float* __restrict__ beta)
{
    int row = blockIdx.x * 8 + (threadIdx.x >> 5);
    int lane = threadIdx.x & 31;
    size_t base = (size_t)row * DD + lane * 16;

    uint4 hv0 = *(const uint4*)(h + base);
    uint4 hv1 = *(const uint4*)(h + base + 8);
    uint4 rv0 = *(const uint4*)(r1 + base);
    uint4 rv1 = *(const uint4*)(r1 + base + 8);

    float x[16];
    {
        const __half2* hh0 = (const __half2*)&hv0;
        const __half2* hh1 = (const __half2*)&hv1;
        const __half2* rr0 = (const __half2*)&rv0;
        const __half2* rr1 = (const __half2*)&rv1;
        #pragma unroll
        for (int i = 0; i < 4; ++i) {
            float2 a = __half22float2(hh0[i]);
            float2 b = __half22float2(rr0[i]);
            x[2 * i]     = a.x + b.x;
            x[2 * i + 1] = a.y + b.y;
            float2 c = __half22float2(hh1[i]);
            float2 d = __half22float2(rr1[i]);
            x[8 + 2 * i]     = c.x + d.x;
            x[8 + 2 * i + 1] = c.y + d.y;
        }
    }
    if (NRES == 2) {
        uint4 sv0 = *(const uint4*)(r2 + base);
        uint4 sv1 = *(const uint4*)(r2 + base + 8);
        const __half2* ss0 = (const __half2*)&sv0;
        const __half2* ss1 = (const __half2*)&sv1;
        #pragma unroll
        for (int i = 0; i < 4; ++i) {
            float2 a = __half22float2(ss0[i]);
            x[2 * i]     += a.x;
            x[2 * i + 1] += a.y;
            float2 b = __half22float2(ss1[i]);
            x[8 + 2 * i]     += b.x;
            x[8 + 2 * i + 1] += b.y;
        }
    }

    float s = 0.0f, sq = 0.0f;
    #pragma unroll
    for (int i = 0; i < 16; ++i) { s += x[i]; sq += x[i] * x[i]; }
    #pragma unroll
    for (int off = 16; off; off >>= 1) {
        s  += __shfl_xor_sync(0xffffffffu, s, off);
        sq += __shfl_xor_sync(0xffffffffu, sq, off);
    }

    float mu = s * (1.0f / DD);
    float var = sq * (1.0f / DD) - mu * mu;
    float rstd = rsqrtf(var + 1e-6f);

    float4 g[4], b4[4];
    #pragma unroll
    for (int i = 0; i < 4; ++i) {
        g[i]  = *(const float4*)&gamma[lane * 16 + i * 4];
        b4[i] = *(const float4*)&beta[lane * 16 + i * 4];
    }

    uint4 o0, o1;
    __half2* oo0 = (__half2*)&o0;
    __half2* oo1 = (__half2*)&o1;
    #pragma unroll
    for (int i = 0; i < 2; ++i) {
        const float* gp = (const float*)&g[i];
        const float* bp = (const float*)&b4[i];
        #pragma unroll
        for (int j = 0; j < 2; ++j) {
            __half2 rr;
            rr.x = __float2half_rn((x[4 * i + 2 * j]     - mu) * rstd * gp[2 * j]     + bp[2 * j]);
            rr.y = __float2half_rn((x[4 * i + 2 * j + 1] - mu) * rstd * gp[2 * j + 1] + bp[2 * j + 1]);
            oo0[2 * i + j] = rr;
        }
    }
    #pragma unroll
    for (int i = 0; i < 2; ++i) {
        const float* gp = (const float*)&g[2 + i];
        const float* bp = (const float*)&b4[2 + i];
        #pragma unroll
        for (int j = 0; j < 2; ++j) {
            __half2 rr;
            rr.x = __float2half_rn((x[8 + 4 * i + 2 * j]     - mu) * rstd * gp[2 * j]     + bp[2 * j]);
            rr.y = __float2half_rn((x[8 + 4 * i + 2 * j + 1] - mu) * rstd * gp[2 * j + 1] + bp[2 * j + 1]);
            oo1[2 * i + j] = rr;
        }
    }

    *(uint4*)(h + base)     = o0;
    *(uint4*)(h + base + 8) = o1;
}

// ---------------------------------------------------------------------------
// Output head (V=21): one warp per row, Wout cached in SMEM, fp16 h input
// ---------------------------------------------------------------------------
__global__ __launch_bounds__(256) void out_proj(
    const __half* __restrict__ h, const float* __restrict__ Wout,
    const float* __restrict__ bout, float* __restrict__ out)
{
    __shared__ float sW[DD * VV];
    for (int i = threadIdx.x; i < DD * VV; i += 256) sW[i] = Wout[i];
    __syncthreads();

    int warp = threadIdx.x >> 5, lane = threadIdx.x & 31;
    int row = blockIdx.x * 8 + warp;
    const __half* hr = h + (size_t)row * DD;

    float acc = 0.0f;
    for (int d = 0; d < DD; d += 4) {
        float2 a = __half22float2(*(const __half2*)(hr + d));
        float2 b = __half22float2(*(const __half2*)(hr + d + 2));
        if (lane < VV) {
            acc += a.x * sW[(d + 0) * VV + lane];
            acc += a.y * sW[(d + 1) * VV + lane];
            acc += b.x * sW[(d + 2) * VV + lane];
            acc += b.y * sW[(d + 3) * VV + lane];
        }
    }
    if (lane < VV) out[(size_t)row * VV + lane] = acc + bout[lane];
}

// ---------------------------------------------------------------------------
// Host launcher
// ---------------------------------------------------------------------------
extern "C" void kernel_launch(void* const* d_in, const int* in_sizes, int n_in,
                              void* d_out, int out_size)
{
    const int*   x       = (const int*)  d_in[0];
    const int*   parents = (const int*)  d_in[1];
    const float* tok     = (const float*)d_in[2];
    const float* pos     = (const float*)d_in[3];
    const float* Wq      = (const float*)d_in[4];
    const float* bq      = (const float*)d_in[5];
    const float* Wk      = (const float*)d_in[6];
    const float* bk      = (const float*)d_in[7];
    const float* Wv      = (const float*)d_in[8];
    const float* bv      = (const float*)d_in[9];
    const float* Wo      = (const float*)d_in[10];
    const float* bo      = (const float*)d_in[11];
    const float* ln1_s   = (const float*)d_in[12];
    const float* ln1_b   = (const float*)d_in[13];
    const float* ln2_s   = (const float*)d_in[14];
    const float* ln2_b   = (const float*)d_in[15];
    const float* W1      = (const float*)d_in[16];
    const float* b1      = (const float*)d_in[17];
    const float* W2      = (const float*)d_in[18];
    const float* b2      = (const float*)d_in[19];
    const float* Wout    = (const float*)d_in[20];
    const float* bout    = (const float*)d_in[21];
    float* out = (float*)d_out;

    float *bqkv;
    __half *qkv, *tmp, *tmp2, *hin, *att, *ff, *w;
    cudaGetSymbolAddress((void**)&qkv,  g_qkv);
    cudaGetSymbolAddress((void**)&tmp,  g_tmp);
    cudaGetSymbolAddress((void**)&tmp2, g_tmp2);
    cudaGetSymbolAddress((void**)&bqkv, g_bqkv);
    cudaGetSymbolAddress((void**)&hin,  g_hin);
    cudaGetSymbolAddress((void**)&att,  g_att);
    cudaGetSymbolAddress((void**)&ff,   g_ff);
    cudaGetSymbolAddress((void**)&w,    g_w);

    cudaFuncSetAttribute(gemm_tc, cudaFuncAttributeMaxDynamicSharedMemorySize, SMEM_GEMM);

    prep_weights<<<NLAYERS * 3072, 256>>>(Wq, Wk, Wv, Wo, W1, W2, w);
    prep_bias<<<NLAYERS * NQKV / 256, 256>>>(bq, bk, bv, bqkv);
    embed_kernel<<<(MM * DD / 4) / 256, 256>>>(x, tok, pos, hin);

    dim3 gQKV(NQKV / BN, MM / BM);       // 12 x 256
    dim3 gD(DD / BN, MM / BM);           // 4 x 256
    dim3 gF(FF / BN, MM / BM);           // 16 x 256
    dim3 gFF2(2 * (DD / BN), MM / BM);   // 8 x 256: split-K=2 linearized in x

    for (int l = 0; l < NLAYERS; ++l) {
        size_t WB = (size_t)l * WPL;

        gemm_tc<<<gQKV, 256, SMEM_GEMM>>>(hin, w + WB + W_QKV, bqkv + (size_t)l * NQKV,
                                          qkv, nullptr, MM, NQKV, DD, DD, 0);

        tree_attn<<<MM / 8, 256>>>(qkv, parents, att);

        gemm_tc<<<gD, 256, SMEM_GEMM>>>(att, w + WB + W_O, bo + (size_t)l * DD,
                                        tmp, nullptr, MM, DD, DD, DD, 0);

        add_ln<1><<<MM / 8, 256>>>(hin, tmp, nullptr,
                                   ln1_s + (size_t)l * DD, ln1_b + (size_t)l * DD);

        gemm_tc<<<gF, 256, SMEM_GEMM>>>(hin, w + WB + W_1, b1 + (size_t)l * FF,
                                        ff, nullptr, MM, FF, DD, DD, 1);

        // FF2: split-K=2 in one launch; z=0 -> tmp (+bias), z=1 -> tmp2
        gemm_tc<<<gFF2, 256, SMEM_GEMM>>>(ff, w + WB + W_2, b2 + (size_t)l * DD,
                                          tmp, tmp2, MM, DD, FF, FF / 2, 0);

        add_ln<2><<<MM / 8, 256>>>(hin, tmp, tmp2,
                                   ln2_s + (size_t)l * DD, ln2_b + (size_t)l * DD);
    }

    out_proj<<<MM / 8, 256>>>(hin, Wout, bout, out);
}

// round 15
// speedup vs baseline: 1.0412x; 1.0412x over previous
#include <cuda_runtime.h>
#include <cuda_fp16.h>
#include <cstdint>

// Problem constants
#define BB 16
#define LL 2048
#define DD 512
#define HH 8
#define DHH 64
#define FF 2048
#define NLAYERS 4
#define VV 21
#define MM (BB * LL)       // 32768
#define NQKV 1536

// ---------------------------------------------------------------------------
// Scratch (device globals; no runtime allocation)
// ---------------------------------------------------------------------------
__device__ __align__(256) __half g_hin[MM * DD];     // residual stream (fp16)
__device__ __align__(256) __half g_qkv[MM * NQKV];
__device__ __align__(256) __half g_tmp[MM * DD];
__device__ __align__(256) __half g_att[MM * DD];
__device__ __align__(256) __half g_ff[MM * FF];
// transposed fp16 weights [N][K] per layer: Wqkv[1536x512], Wo[512x512], W1[2048x512], W2[512x2048]
#define WPL 3145728
#define W_QKV 0
#define W_O   786432
#define W_1   1048576
#define W_2   2097152
__device__ __align__(256) __half g_w[NLAYERS * WPL];
__device__ __align__(256) float g_bqkv[NLAYERS * NQKV];

// ---------------------------------------------------------------------------
// PTX helpers (generic sm_80+: cp.async, ldmatrix, mma.sync)
// ---------------------------------------------------------------------------
__device__ __forceinline__ uint32_t smem_u32(const void* p) {
    uint32_t a;
    asm("{ .reg .u64 t; cvta.to.shared.u64 t, %1; cvt.u32.u64 %0, t; }" : "=r"(a) : "l"(p));
    return a;
}
__device__ __forceinline__ void cp_async16(uint32_t saddr, const void* gaddr) {
    asm volatile("cp.async.cg.shared.global [%0], [%1], 16;" :: "r"(saddr), "l"(gaddr));
}
#define CP_COMMIT() asm volatile("cp.async.commit_group;" ::: "memory")
#define CP_WAIT1()  asm volatile("cp.async.wait_group 1;" ::: "memory")

__device__ __forceinline__ void ldsm_x4(uint32_t addr, uint32_t& r0, uint32_t& r1, uint32_t& r2, uint32_t& r3) {
    asm volatile("ldmatrix.sync.aligned.m8n8.x4.shared.b16 {%0,%1,%2,%3}, [%4];"
                 : "=r"(r0), "=r"(r1), "=r"(r2), "=r"(r3) : "r"(addr));
}
__device__ __forceinline__ void mma16816(float* c, const uint32_t* a, uint32_t b0, uint32_t b1) {
    asm volatile("mma.sync.aligned.m16n8k16.row.col.f32.f16.f16.f32 "
                 "{%0,%1,%2,%3}, {%4,%5,%6,%7}, {%8,%9}, {%0,%1,%2,%3};"
                 : "+f"(c[0]), "+f"(c[1]), "+f"(c[2]), "+f"(c[3])
                 : "r"(a[0]), "r"(a[1]), "r"(a[2]), "r"(a[3]), "r"(b0), "r"(b1));
}

// dot-accumulate 8 halves (one uint4) of a and b into acc (fp32)
__device__ __forceinline__ void dot8(float& acc, uint4 a, uint4 b) {
    const __half2* ah = (const __half2*)&a;
    const __half2* bh = (const __half2*)&b;
    #pragma unroll
    for (int i = 0; i < 4; ++i) {
        float2 af = __half22float2(ah[i]);
        float2 bf = __half22float2(bh[i]);
        acc += af.x * bf.x + af.y * bf.y;
    }
}

// ---------------------------------------------------------------------------
// Fused weight preprocess: ONE kernel transposes all 24 matrices to [N][K] fp16.
// ---------------------------------------------------------------------------
__global__ __launch_bounds__(256) void prep_weights(
    const float* __restrict__ Wq, const float* __restrict__ Wk,
    const float* __restrict__ Wv, const float* __restrict__ Wo,
    const float* __restrict__ W1, const float* __restrict__ W2,
    __half* __restrict__ w)
{
    __shared__ float tile[32][33];
    int b = blockIdx.x;
    int layer = b / 3072, r = b % 3072;
    size_t lw = (size_t)layer * WPL;
    const float* in; __half* o; int K, N, t;
    if (r < 256)       { in = Wq + (size_t)layer * 262144;  o = w + lw + W_QKV;           K = 512;  N = 512;  t = r; }
    else if (r < 512)  { in = Wk + (size_t)layer * 262144;  o = w + lw + W_QKV + 262144;  K = 512;  N = 512;  t = r - 256; }
    else if (r < 768)  { in = Wv + (size_t)layer * 262144;  o = w + lw + W_QKV + 524288;  K = 512;  N = 512;  t = r - 512; }
    else if (r < 1024) { in = Wo + (size_t)layer * 262144;  o = w + lw + W_O;             K = 512;  N = 512;  t = r - 768; }
    else if (r < 2048) { in = W1 + (size_t)layer * 1048576; o = w + lw + W_1;             K = 512;  N = 2048; t = r - 1024; }
    else               { in = W2 + (size_t)layer * 1048576; o = w + lw + W_2;             K = 2048; N = 512;  t = r - 2048; }

    int ntn = N / 32;
    int n0 = (t % ntn) * 32, k0 = (t / ntn) * 32;
    int tx = threadIdx.x & 31, ty = threadIdx.x >> 5;   // ty 0..7
    #pragma unroll
    for (int i = 0; i < 4; ++i) {
        int k = k0 + ty + i * 8;
        tile[ty + i * 8][tx] = in[(size_t)k * N + n0 + tx];
    }
    __syncthreads();
    #pragma unroll
    for (int i = 0; i < 4; ++i) {
        int n = n0 + ty + i * 8;
        o[(size_t)n * K + k0 + tx] = __float2half_rn(tile[tx][ty + i * 8]);
    }
}

// All layers' QKV biases in one kernel
__global__ __launch_bounds__(256) void prep_bias(
    const float* __restrict__ bq, const float* __restrict__ bk,
    const float* __restrict__ bv, float* __restrict__ out)
{
    int i = blockIdx.x * 256 + threadIdx.x;   // over NLAYERS*1536
    int layer = i / NQKV, j = i - layer * NQKV;
    float v = (j < 512) ? bq[layer * 512 + j]
            : (j < 1024 ? bk[layer * 512 + j - 512] : bv[layer * 512 + j - 1024]);
    out[i] = v;
}

// ---------------------------------------------------------------------------
// Embedding: h16 = (half)(tok[x] + pos)
// ---------------------------------------------------------------------------
__global__ __launch_bounds__(256) void embed_kernel(
    const int* __restrict__ x, const float* __restrict__ tok,
    const float* __restrict__ pos, __half* __restrict__ oh)
{
    int i = blockIdx.x * blockDim.x + threadIdx.x;   // over MM*DD/4
    int bl = i >> 7;
    int d4 = (i & 127) << 2;
    int l  = bl & (LL - 1);
    int t  = x[bl];
    float4 te = *(const float4*)&tok[t * DD + d4];
    float4 pe = *(const float4*)&pos[l * DD + d4];
    size_t base = (size_t)bl * DD + d4;
    __half2 p0; p0.x = __float2half_rn(te.x + pe.x); p0.y = __float2half_rn(te.y + pe.y);
    __half2 p1; p1.x = __float2half_rn(te.z + pe.z); p1.y = __float2half_rn(te.w + pe.w);
    *(__half2*)&oh[base] = p0; *(__half2*)&oh[base + 2] = p1;
}

// ---------------------------------------------------------------------------
// Tensor-core GEMM:  C[M,N] = A[M,K](fp16 rm) @ W[N,K](fp16, B col-major) + bias
// BM=128, BN=128, BK=64, 256 threads / 8 warps, warp tile 64x32 (grid 2Mx4N),
// 2-stage cp.async pipeline, 144B-padded rows (conflict-free ldmatrix).
// At the sm_100 legacy mma.sync issue floor (~278 TF/s) — verified invariant
// across 5 schedule variants. Proven-best configuration (R10).
// ---------------------------------------------------------------------------
#define BM 128
#define BN 128
#define BK 64
#define PAD_STRIDE 144           // 128B row + 16B pad
#define TILE_BYTES 18432         // 128 * 144
#define STAGE_BYTES 36864
#define SMEM_GEMM (2 * STAGE_BYTES)

__global__ __launch_bounds__(256, 2) void gemm_tc(
    const __half* __restrict__ A, const __half* __restrict__ B,
    const float* __restrict__ bias, __half* __restrict__ outH,
    int M, int N, int K, int relu)
{
    extern __shared__ char smem[];
    const uint32_t sb = smem_u32(smem);
    const int tid = threadIdx.x, wid = tid >> 5, lane = tid & 31;
    const int warpM = wid >> 2, warpN = wid & 3;       // 2 x 4 warp grid

    const int rowBase = blockIdx.y * BM;
    const int nBase = blockIdx.x * BN;

    auto load_stage = [&](int stage, int kc) {
        uint32_t st = sb + (uint32_t)(stage & 1) * STAGE_BYTES;
        #pragma unroll
        for (int i = 0; i < 4; ++i) {
            int c = tid + i * 256;            // chunk id 0..1023
            int row = c >> 3;
            int kch = c & 7;                   // 16B chunk within 128B row
            uint32_t so = st + row * PAD_STRIDE + kch * 16;
            cp_async16(so, A + (size_t)(rowBase + row) * K + kc + kch * 8);
            cp_async16(so + TILE_BYTES, B + (size_t)(nBase + row) * K + kc + kch * 8);
        }
        CP_COMMIT();
    };

    float acc[4][4][4];
    #pragma unroll
    for (int mi = 0; mi < 4; ++mi)
        #pragma unroll
        for (int ni = 0; ni < 4; ++ni)
            #pragma unroll
            for (int j = 0; j < 4; ++j) acc[mi][ni][j] = 0.0f;

    const int S = K / BK;
    load_stage(0, 0);
    load_stage(1, BK);

    const int r8 = lane & 7, mt = lane >> 3;
    uint32_t aOff[4], bOff[2];
    #pragma unroll
    for (int mi = 0; mi < 4; ++mi)
        aOff[mi] = (uint32_t)((warpM * 64 + mi * 16 + (mt & 1) * 8 + r8) * PAD_STRIDE + ((mt >> 1) * 8) * 2);
    #pragma unroll
    for (int g = 0; g < 2; ++g)
        bOff[g] = (uint32_t)(TILE_BYTES + (warpN * 32 + g * 16 + (mt >> 1) * 8 + r8) * PAD_STRIDE + ((mt & 1) * 8) * 2);

    for (int it = 0; it < S; ++it) {
        CP_WAIT1();                 // stage it resident (stage it+1 may be in flight)
        __syncthreads();

        uint32_t st = sb + (uint32_t)(it & 1) * STAGE_BYTES;
        #pragma unroll
        for (int ks = 0; ks < 4; ++ks) {      // 4 x K16 per BK=64
            uint32_t af[4][4], bf[2][4];
            #pragma unroll
            for (int g = 0; g < 2; ++g)
                ldsm_x4(st + bOff[g] + ks * 32, bf[g][0], bf[g][1], bf[g][2], bf[g][3]);
            #pragma unroll
            for (int mi = 0; mi < 4; ++mi)
                ldsm_x4(st + aOff[mi] + ks * 32, af[mi][0], af[mi][1], af[mi][2], af[mi][3]);
            #pragma unroll
            for (int mi = 0; mi < 4; ++mi)
                #pragma unroll
                for (int g = 0; g < 2; ++g) {
                    mma16816(acc[mi][2 * g],     af[mi], bf[g][0], bf[g][1]);
                    mma16816(acc[mi][2 * g + 1], af[mi], bf[g][2], bf[g][3]);
                }
        }
        __syncthreads();            // all warps done reading buffer it&1
        if (it + 2 < S) load_stage(it + 2, (it + 2) * BK);
        else CP_COMMIT();           // keep group count consistent
    }

    // epilogue: fp16 out (+optional relu)
    const int mrow0 = rowBase + warpM * 64 + (lane >> 2);
    const int ncol0 = nBase + warpN * 32 + (lane & 3) * 2;
    #pragma unroll
    for (int mi = 0; mi < 4; ++mi) {
        #pragma unroll
        for (int ni = 0; ni < 4; ++ni) {
            int n = ncol0 + ni * 8;
            float b0 = bias[n], b1 = bias[n + 1];
            int m0 = mrow0 + mi * 16;
            float v00 = acc[mi][ni][0] + b0, v01 = acc[mi][ni][1] + b1;
            float v10 = acc[mi][ni][2] + b0, v11 = acc[mi][ni][3] + b1;
            if (relu) {
                v00 = fmaxf(v00, 0.0f); v01 = fmaxf(v01, 0.0f);
                v10 = fmaxf(v10, 0.0f); v11 = fmaxf(v11, 0.0f);
            }
            __half2 h0, h1;
            h0.x = __float2half_rn(v00); h0.y = __float2half_rn(v01);
            h1.x = __float2half_rn(v10); h1.y = __float2half_rn(v11);
            *(__half2*)&outH[(size_t)m0 * N + n] = h0;
            *(__half2*)&outH[(size_t)(m0 + 8) * N + n] = h1;
        }
    }
}

// ---------------------------------------------------------------------------
// Tree attention: ONE WARP per token (b,l), all 8 heads, 16B loads.
// ---------------------------------------------------------------------------
__global__ __launch_bounds__(256) void tree_attn(
    const __half* __restrict__ qkv, const int* __restrict__ parents,
    __half* __restrict__ oh)
{
    int bl = blockIdx.x * 8 + (threadIdx.x >> 5);
    int lane = threadIdx.x & 31;
    int l = bl & (LL - 1);

    int p = parents[l];
    int pk = (p >= 0) ? (p + 1) : l;
    int pbl = (bl - l) + pk;

    size_t rb  = (size_t)bl  * NQKV + lane * 16;
    size_t prb = (size_t)pbl * NQKV + lane * 16;

    uint4 q0  = *(const uint4*)(qkv + rb);
    uint4 q1  = *(const uint4*)(qkv + rb + 8);
    uint4 k0  = *(const uint4*)(qkv + rb + 512);
    uint4 k1  = *(const uint4*)(qkv + rb + 520);
    uint4 kp0 = *(const uint4*)(qkv + prb + 512);
    uint4 kp1 = *(const uint4*)(qkv + prb + 520);

    float d0 = 0.0f, d1 = 0.0f;
    dot8(d0, q0, k0);  dot8(d0, q1, k1);
    dot8(d1, q0, kp0); dot8(d1, q1, kp1);

    // reduce within 4-lane head group
    #pragma unroll
    for (int off = 1; off < 4; off <<= 1) {
        d0 += __shfl_xor_sync(0xffffffffu, d0, off);
        d1 += __shfl_xor_sync(0xffffffffu, d1, off);
    }

    const float scale = 0.125f;   // 1/sqrt(64)
    float s0 = d0 * scale;
    float s1 = (p >= 0) ? d1 * scale : -1e9f;
    float m  = fmaxf(s0, s1);
    float e0 = __expf(s0 - m);
    float e1 = __expf(s1 - m);
    float inv = 1.0f / (e0 + e1);
    float a0 = e0 * inv, a1 = e1 * inv;

    uint4 v0  = *(const uint4*)(qkv + rb + 1024);
    uint4 v1  = *(const uint4*)(qkv + rb + 1032);
    uint4 vp0 = *(const uint4*)(qkv + prb + 1024);
    uint4 vp1 = *(const uint4*)(qkv + prb + 1032);

    uint4 o0, o1;
    {
        const __half2* vs = (const __half2*)&v0;
        const __half2* vp = (const __half2*)&vp0;
        __half2* oo = (__half2*)&o0;
        #pragma unroll
        for (int i = 0; i < 4; ++i) {
            float2 a = __half22float2(vs[i]);
            float2 b = __half22float2(vp[i]);
            __half2 r;
            r.x = __float2half_rn(a0 * a.x + a1 * b.x);
            r.y = __float2half_rn(a0 * a.y + a1 * b.y);
            oo[i] = r;
        }
        const __half2* vs1 = (const __half2*)&v1;
        const __half2* vp1h = (const __half2*)&vp1;
        __half2* oo1 = (__half2*)&o1;
        #pragma unroll
        for (int i = 0; i < 4; ++i) {
            float2 a = __half22float2(vs1[i]);
            float2 b = __half22float2(vp1h[i]);
            __half2 r;
            r.x = __float2half_rn(a0 * a.x + a1 * b.x);
            r.y = __float2half_rn(a0 * a.y + a1 * b.y);
            oo1[i] = r;
        }
    }

    size_t ob = (size_t)bl * DD + lane * 16;
    *(uint4*)(oh + ob)     = o0;
    *(uint4*)(oh + ob + 8) = o1;
}

// ---------------------------------------------------------------------------
// Fused residual-add + LayerNorm: ONE WARP per row, shfl-only, 16B loads.
// ---------------------------------------------------------------------------
__global__ __launch_bounds__(256) void add_ln(
    __half* __restrict__ h, const __half* __restrict__ r,
    const float* __restrict__ gamma, const float* __restrict__ beta)
{
    int row = blockIdx.x * 8 + (threadIdx.x >> 5);
    int lane = threadIdx.x & 31;
    size_t base = (size_t)row * DD + lane * 16;

    uint4 hv0 = *(const uint4*)(h + base);
    uint4 hv1 = *(const uint4*)(h + base + 8);
    uint4 rv0 = *(const uint4*)(r + base);
    uint4 rv1 = *(const uint4*)(r + base + 8);

    float x[16];
    {
        const __half2* hh0 = (const __half2*)&hv0;
        const __half2* hh1 = (const __half2*)&hv1;
        const __half2* rr0 = (const __half2*)&rv0;
        const __half2* rr1 = (const __half2*)&rv1;
        #pragma unroll
        for (int i = 0; i < 4; ++i) {
            float2 a = __half22float2(hh0[i]);
            float2 b = __half22float2(rr0[i]);
            x[2 * i]     = a.x + b.x;
            x[2 * i + 1] = a.y + b.y;
            float2 c = __half22float2(hh1[i]);
            float2 d = __half22float2(rr1[i]);
            x[8 + 2 * i]     = c.x + d.x;
            x[8 + 2 * i + 1] = c.y + d.y;
        }
    }

    float s = 0.0f, sq = 0.0f;
    #pragma unroll
    for (int i = 0; i < 16; ++i) { s += x[i]; sq += x[i] * x[i]; }
    #pragma unroll
    for (int off = 16; off; off >>= 1) {
        s  += __shfl_xor_sync(0xffffffffu, s, off);
        sq += __shfl_xor_sync(0xffffffffu, sq, off);
    }

    float mu = s * (1.0f / DD);
    float var = sq * (1.0f / DD) - mu * mu;
    float rstd = rsqrtf(var + 1e-6f);

    float4 g[4], b4[4];
    #pragma unroll
    for (int i = 0; i < 4; ++i) {
        g[i]  = *(const float4*)&gamma[lane * 16 + i * 4];
        b4[i] = *(const float4*)&beta[lane * 16 + i * 4];
    }

    uint4 o0, o1;
    __half2* oo0 = (__half2*)&o0;
    __half2* oo1 = (__half2*)&o1;
    #pragma unroll
    for (int i = 0; i < 2; ++i) {
        const float* gp = (const float*)&g[i];
        const float* bp = (const float*)&b4[i];
        #pragma unroll
        for (int j = 0; j < 2; ++j) {
            __half2 rr;
            rr.x = __float2half_rn((x[4 * i + 2 * j]     - mu) * rstd * gp[2 * j]     + bp[2 * j]);
            rr.y = __float2half_rn((x[4 * i + 2 * j + 1] - mu) * rstd * gp[2 * j + 1] + bp[2 * j + 1]);
            oo0[2 * i + j] = rr;
        }
    }
    #pragma unroll
    for (int i = 0; i < 2; ++i) {
        const float* gp = (const float*)&g[2 + i];
        const float* bp = (const float*)&b4[2 + i];
        #pragma unroll
        for (int j = 0; j < 2; ++j) {
            __half2 rr;
            rr.x = __float2half_rn((x[8 + 4 * i + 2 * j]     - mu) * rstd * gp[2 * j]     + bp[2 * j]);
            rr.y = __float2half_rn((x[8 + 4 * i + 2 * j + 1] - mu) * rstd * gp[2 * j + 1] + bp[2 * j + 1]);
            oo1[2 * i + j] = rr;
        }
    }

    *(uint4*)(h + base)     = o0;
    *(uint4*)(h + base + 8) = o1;
}

// ---------------------------------------------------------------------------
// Output head (V=21): one warp per row, Wout cached in SMEM, fp16 h input
// ---------------------------------------------------------------------------
__global__ __launch_bounds__(256) void out_proj(
    const __half* __restrict__ h, const float* __restrict__ Wout,
    const float* __restrict__ bout, float* __restrict__ out)
{
    __shared__ float sW[DD * VV];
    for (int i = threadIdx.x; i < DD * VV; i += 256) sW[i] = Wout[i];
    __syncthreads();

    int warp = threadIdx.x >> 5, lane = threadIdx.x & 31;
    int row = blockIdx.x * 8 + warp;
    const __half* hr = h + (size_t)row * DD;

    float acc = 0.0f;
    for (int d = 0; d < DD; d += 4) {
        float2 a = __half22float2(*(const __half2*)(hr + d));
        float2 b = __half22float2(*(const __half2*)(hr + d + 2));
        if (lane < VV) {
            acc += a.x * sW[(d + 0) * VV + lane];
            acc += a.y * sW[(d + 1) * VV + lane];
            acc += b.x * sW[(d + 2) * VV + lane];
            acc += b.y * sW[(d + 3) * VV + lane];
        }
    }
    if (lane < VV) out[(size_t)row * VV + lane] = acc + bout[lane];
}

// ---------------------------------------------------------------------------
// Host launcher
// ---------------------------------------------------------------------------
extern "C" void kernel_launch(void* const* d_in, const int* in_sizes, int n_in,
                              void* d_out, int out_size)
{
    const int*   x       = (const int*)  d_in[0];
    const int*   parents = (const int*)  d_in[1];
    const float* tok     = (const float*)d_in[2];
    const float* pos     = (const float*)d_in[3];
    const float* Wq      = (const float*)d_in[4];
    const float* bq      = (const float*)d_in[5];
    const float* Wk      = (const float*)d_in[6];
    const float* bk      = (const float*)d_in[7];
    const float* Wv      = (const float*)d_in[8];
    const float* bv      = (const float*)d_in[9];
    const float* Wo      = (const float*)d_in[10];
    const float* bo      = (const float*)d_in[11];
    const float* ln1_s   = (const float*)d_in[12];
    const float* ln1_b   = (const float*)d_in[13];
    const float* ln2_s   = (const float*)d_in[14];
    const float* ln2_b   = (const float*)d_in[15];
    const float* W1      = (const float*)d_in[16];
    const float* b1      = (const float*)d_in[17];
    const float* W2      = (const float*)d_in[18];
    const float* b2      = (const float*)d_in[19];
    const float* Wout    = (const float*)d_in[20];
    const float* bout    = (const float*)d_in[21];
    float* out = (float*)d_out;

    float *bqkv;
    __half *qkv, *tmp, *hin, *att, *ff, *w;
    cudaGetSymbolAddress((void**)&qkv,  g_qkv);
    cudaGetSymbolAddress((void**)&tmp,  g_tmp);
    cudaGetSymbolAddress((void**)&bqkv, g_bqkv);
    cudaGetSymbolAddress((void**)&hin,  g_hin);
    cudaGetSymbolAddress((void**)&att,  g_att);
    cudaGetSymbolAddress((void**)&ff,   g_ff);
    cudaGetSymbolAddress((void**)&w,    g_w);

    cudaFuncSetAttribute(gemm_tc, cudaFuncAttributeMaxDynamicSharedMemorySize, SMEM_GEMM);

    prep_weights<<<NLAYERS * 3072, 256>>>(Wq, Wk, Wv, Wo, W1, W2, w);
    prep_bias<<<NLAYERS * NQKV / 256, 256>>>(bq, bk, bv, bqkv);
    embed_kernel<<<(MM * DD / 4) / 256, 256>>>(x, tok, pos, hin);

    dim3 gQKV(NQKV / BN, MM / BM);   // 12 x 256
    dim3 gD(DD / BN, MM / BM);       // 4 x 256
    dim3 gF(FF / BN, MM / BM);       // 16 x 256

    for (int l = 0; l < NLAYERS; ++l) {
        size_t WB = (size_t)l * WPL;

        gemm_tc<<<gQKV, 256, SMEM_GEMM>>>(hin, w + WB + W_QKV, bqkv + (size_t)l * NQKV,
                                          qkv, MM, NQKV, DD, 0);

        tree_attn<<<MM / 8, 256>>>(qkv, parents, att);

        gemm_tc<<<gD, 256, SMEM_GEMM>>>(att, w + WB + W_O, bo + (size_t)l * DD,
                                        tmp, MM, DD, DD, 0);

        add_ln<<<MM / 8, 256>>>(hin, tmp, ln1_s + (size_t)l * DD, ln1_b + (size_t)l * DD);

        gemm_tc<<<gF, 256, SMEM_GEMM>>>(hin, w + WB + W_1, b1 + (size_t)l * FF,
                                        ff, MM, FF, DD, 1);

        gemm_tc<<<gD, 256, SMEM_GEMM>>>(ff, w + WB + W_2, b2 + (size_t)l * DD,
                                        tmp, MM, DD, FF, 0);

        add_ln<<<MM / 8, 256>>>(hin, tmp, ln2_s + (size_t)l * DD, ln2_b + (size_t)l * DD);
    }

    out_proj<<<MM / 8, 256>>>(hin, Wout, bout, out);
}

// round 16
// speedup vs baseline: 1.0421x; 1.0009x over previous
#include <cuda_runtime.h>
#include <cuda_fp16.h>
#include <cstdint>

// Problem constants
#define BB 16
#define LL 2048
#define DD 512
#define HH 8
#define DHH 64
#define FF 2048
#define NLAYERS 4
#define VV 21
#define MM (BB * LL)       // 32768
#define NQKV 1536

// ---------------------------------------------------------------------------
// Scratch (device globals; no runtime allocation)
// ---------------------------------------------------------------------------
__device__ __align__(256) __half g_hin[MM * DD];     // residual stream (fp16)
__device__ __align__(256) __half g_qkv[MM * NQKV];
__device__ __align__(256) __half g_tmp[MM * DD];
__device__ __align__(256) __half g_att[MM * DD];
__device__ __align__(256) __half g_ff[MM * FF];
// transposed fp16 weights [N][K] per layer: Wqkv[1536x512], Wo[512x512], W1[2048x512], W2[512x2048]
#define WPL 3145728
#define W_QKV 0
#define W_O   786432
#define W_1   1048576
#define W_2   2097152
__device__ __align__(256) __half g_w[NLAYERS * WPL];
__device__ __align__(256) float g_bqkv[NLAYERS * NQKV];

// ---------------------------------------------------------------------------
// PTX helpers (generic sm_80+: cp.async, ldmatrix, mma.sync)
// ---------------------------------------------------------------------------
__device__ __forceinline__ uint32_t smem_u32(const void* p) {
    uint32_t a;
    asm("{ .reg .u64 t; cvta.to.shared.u64 t, %1; cvt.u32.u64 %0, t; }" : "=r"(a) : "l"(p));
    return a;
}
__device__ __forceinline__ void cp_async16(uint32_t saddr, const void* gaddr) {
    asm volatile("cp.async.cg.shared.global [%0], [%1], 16;" :: "r"(saddr), "l"(gaddr));
}
#define CP_COMMIT() asm volatile("cp.async.commit_group;" ::: "memory")
#define CP_WAIT1()  asm volatile("cp.async.wait_group 1;" ::: "memory")

__device__ __forceinline__ void ldsm_x4(uint32_t addr, uint32_t& r0, uint32_t& r1, uint32_t& r2, uint32_t& r3) {
    asm volatile("ldmatrix.sync.aligned.m8n8.x4.shared.b16 {%0,%1,%2,%3}, [%4];"
                 : "=r"(r0), "=r"(r1), "=r"(r2), "=r"(r3) : "r"(addr));
}
__device__ __forceinline__ void mma16816(float* c, const uint32_t* a, uint32_t b0, uint32_t b1) {
    asm volatile("mma.sync.aligned.m16n8k16.row.col.f32.f16.f16.f32 "
                 "{%0,%1,%2,%3}, {%4,%5,%6,%7}, {%8,%9}, {%0,%1,%2,%3};"
                 : "+f"(c[0]), "+f"(c[1]), "+f"(c[2]), "+f"(c[3])
                 : "r"(a[0]), "r"(a[1]), "r"(a[2]), "r"(a[3]), "r"(b0), "r"(b1));
}

// dot-accumulate 8 halves (one uint4) of a and b into acc (fp32)
__device__ __forceinline__ void dot8(float& acc, uint4 a, uint4 b) {
    const __half2* ah = (const __half2*)&a;
    const __half2* bh = (const __half2*)&b;
    #pragma unroll
    for (int i = 0; i < 4; ++i) {
        float2 af = __half22float2(ah[i]);
        float2 bf = __half22float2(bh[i]);
        acc += af.x * bf.x + af.y * bf.y;
    }
}

// ---------------------------------------------------------------------------
// Fused weight preprocess: ONE kernel transposes all 24 matrices to [N][K] fp16.
// ---------------------------------------------------------------------------
__global__ __launch_bounds__(256) void prep_weights(
    const float* __restrict__ Wq, const float* __restrict__ Wk,
    const float* __restrict__ Wv, const float* __restrict__ Wo,
    const float* __restrict__ W1, const float* __restrict__ W2,
    __half* __restrict__ w)
{
    __shared__ float tile[32][33];
    int b = blockIdx.x;
    int layer = b / 3072, r = b % 3072;
    size_t lw = (size_t)layer * WPL;
    const float* in; __half* o; int K, N, t;
    if (r < 256)       { in = Wq + (size_t)layer * 262144;  o = w + lw + W_QKV;           K = 512;  N = 512;  t = r; }
    else if (r < 512)  { in = Wk + (size_t)layer * 262144;  o = w + lw + W_QKV + 262144;  K = 512;  N = 512;  t = r - 256; }
    else if (r < 768)  { in = Wv + (size_t)layer * 262144;  o = w + lw + W_QKV + 524288;  K = 512;  N = 512;  t = r - 512; }
    else if (r < 1024) { in = Wo + (size_t)layer * 262144;  o = w + lw + W_O;             K = 512;  N = 512;  t = r - 768; }
    else if (r < 2048) { in = W1 + (size_t)layer * 1048576; o = w + lw + W_1;             K = 512;  N = 2048; t = r - 1024; }
    else               { in = W2 + (size_t)layer * 1048576; o = w + lw + W_2;             K = 2048; N = 512;  t = r - 2048; }

    int ntn = N / 32;
    int n0 = (t % ntn) * 32, k0 = (t / ntn) * 32;
    int tx = threadIdx.x & 31, ty = threadIdx.x >> 5;   // ty 0..7
    #pragma unroll
    for (int i = 0; i < 4; ++i) {
        int k = k0 + ty + i * 8;
        tile[ty + i * 8][tx] = in[(size_t)k * N + n0 + tx];
    }
    __syncthreads();
    #pragma unroll
    for (int i = 0; i < 4; ++i) {
        int n = n0 + ty + i * 8;
        o[(size_t)n * K + k0 + tx] = __float2half_rn(tile[tx][ty + i * 8]);
    }
}

// All layers' QKV biases in one kernel
__global__ __launch_bounds__(256) void prep_bias(
    const float* __restrict__ bq, const float* __restrict__ bk,
    const float* __restrict__ bv, float* __restrict__ out)
{
    int i = blockIdx.x * 256 + threadIdx.x;   // over NLAYERS*1536
    int layer = i / NQKV, j = i - layer * NQKV;
    float v = (j < 512) ? bq[layer * 512 + j]
            : (j < 1024 ? bk[layer * 512 + j - 512] : bv[layer * 512 + j - 1024]);
    out[i] = v;
}

// ---------------------------------------------------------------------------
// Embedding: h16 = (half)(tok[x] + pos)
// ---------------------------------------------------------------------------
__global__ __launch_bounds__(256) void embed_kernel(
    const int* __restrict__ x, const float* __restrict__ tok,
    const float* __restrict__ pos, __half* __restrict__ oh)
{
    int i = blockIdx.x * blockDim.x + threadIdx.x;   // over MM*DD/4
    int bl = i >> 7;
    int d4 = (i & 127) << 2;
    int l  = bl & (LL - 1);
    int t  = x[bl];
    float4 te = *(const float4*)&tok[t * DD + d4];
    float4 pe = *(const float4*)&pos[l * DD + d4];
    size_t base = (size_t)bl * DD + d4;
    __half2 p0; p0.x = __float2half_rn(te.x + pe.x); p0.y = __float2half_rn(te.y + pe.y);
    __half2 p1; p1.x = __float2half_rn(te.z + pe.z); p1.y = __float2half_rn(te.w + pe.w);
    *(__half2*)&oh[base] = p0; *(__half2*)&oh[base + 2] = p1;
}

// ---------------------------------------------------------------------------
// Tensor-core GEMM:  C[M,N] = A[M,K](fp16 rm) @ W[N,K](fp16, B col-major) + bias
// BM=128, BN=128, BK=64, 256 threads / 8 warps, warp tile 64x32 (grid 2Mx4N),
// 2-stage cp.async pipeline, 144B-padded rows (conflict-free ldmatrix).
// At the sm_100 legacy mma.sync issue floor (~278 TF/s) — verified invariant
// across 5 schedule variants. Proven-best configuration.
// ---------------------------------------------------------------------------
#define BM 128
#define BN 128
#define BK 64
#define PAD_STRIDE 144           // 128B row + 16B pad
#define TILE_BYTES 18432         // 128 * 144
#define STAGE_BYTES 36864
#define SMEM_GEMM (2 * STAGE_BYTES)

__global__ __launch_bounds__(256, 2) void gemm_tc(
    const __half* __restrict__ A, const __half* __restrict__ B,
    const float* __restrict__ bias, __half* __restrict__ outH,
    int M, int N, int K, int relu)
{
    extern __shared__ char smem[];
    const uint32_t sb = smem_u32(smem);
    const int tid = threadIdx.x, wid = tid >> 5, lane = tid & 31;
    const int warpM = wid >> 2, warpN = wid & 3;       // 2 x 4 warp grid

    const int rowBase = blockIdx.y * BM;
    const int nBase = blockIdx.x * BN;

    auto load_stage = [&](int stage, int kc) {
        uint32_t st = sb + (uint32_t)(stage & 1) * STAGE_BYTES;
        #pragma unroll
        for (int i = 0; i < 4; ++i) {
            int c = tid + i * 256;            // chunk id 0..1023
            int row = c >> 3;
            int kch = c & 7;                   // 16B chunk within 128B row
            uint32_t so = st + row * PAD_STRIDE + kch * 16;
            cp_async16(so, A + (size_t)(rowBase + row) * K + kc + kch * 8);
            cp_async16(so + TILE_BYTES, B + (size_t)(nBase + row) * K + kc + kch * 8);
        }
        CP_COMMIT();
    };

    float acc[4][4][4];
    #pragma unroll
    for (int mi = 0; mi < 4; ++mi)
        #pragma unroll
        for (int ni = 0; ni < 4; ++ni)
            #pragma unroll
            for (int j = 0; j < 4; ++j) acc[mi][ni][j] = 0.0f;

    const int S = K / BK;
    load_stage(0, 0);
    load_stage(1, BK);

    const int r8 = lane & 7, mt = lane >> 3;
    uint32_t aOff[4], bOff[2];
    #pragma unroll
    for (int mi = 0; mi < 4; ++mi)
        aOff[mi] = (uint32_t)((warpM * 64 + mi * 16 + (mt & 1) * 8 + r8) * PAD_STRIDE + ((mt >> 1) * 8) * 2);
    #pragma unroll
    for (int g = 0; g < 2; ++g)
        bOff[g] = (uint32_t)(TILE_BYTES + (warpN * 32 + g * 16 + (mt >> 1) * 8 + r8) * PAD_STRIDE + ((mt & 1) * 8) * 2);

    for (int it = 0; it < S; ++it) {
        CP_WAIT1();                 // stage it resident (stage it+1 may be in flight)
        __syncthreads();

        uint32_t st = sb + (uint32_t)(it & 1) * STAGE_BYTES;
        #pragma unroll
        for (int ks = 0; ks < 4; ++ks) {      // 4 x K16 per BK=64
            uint32_t af[4][4], bf[2][4];
            #pragma unroll
            for (int g = 0; g < 2; ++g)
                ldsm_x4(st + bOff[g] + ks * 32, bf[g][0], bf[g][1], bf[g][2], bf[g][3]);
            #pragma unroll
            for (int mi = 0; mi < 4; ++mi)
                ldsm_x4(st + aOff[mi] + ks * 32, af[mi][0], af[mi][1], af[mi][2], af[mi][3]);
            #pragma unroll
            for (int mi = 0; mi < 4; ++mi)
                #pragma unroll
                for (int g = 0; g < 2; ++g) {
                    mma16816(acc[mi][2 * g],     af[mi], bf[g][0], bf[g][1]);
                    mma16816(acc[mi][2 * g + 1], af[mi], bf[g][2], bf[g][3]);
                }
        }
        __syncthreads();            // all warps done reading buffer it&1
        if (it + 2 < S) load_stage(it + 2, (it + 2) * BK);
        else CP_COMMIT();           // keep group count consistent
    }

    // epilogue: fp16 out (+optional relu)
    const int mrow0 = rowBase + warpM * 64 + (lane >> 2);
    const int ncol0 = nBase + warpN * 32 + (lane & 3) * 2;
    #pragma unroll
    for (int mi = 0; mi < 4; ++mi) {
        #pragma unroll
        for (int ni = 0; ni < 4; ++ni) {
            int n = ncol0 + ni * 8;
            float b0 = bias[n], b1 = bias[n + 1];
            int m0 = mrow0 + mi * 16;
            float v00 = acc[mi][ni][0] + b0, v01 = acc[mi][ni][1] + b1;
            float v10 = acc[mi][ni][2] + b0, v11 = acc[mi][ni][3] + b1;
            if (relu) {
                v00 = fmaxf(v00, 0.0f); v01 = fmaxf(v01, 0.0f);
                v10 = fmaxf(v10, 0.0f); v11 = fmaxf(v11, 0.0f);
            }
            __half2 h0, h1;
            h0.x = __float2half_rn(v00); h0.y = __float2half_rn(v01);
            h1.x = __float2half_rn(v10); h1.y = __float2half_rn(v11);
            *(__half2*)&outH[(size_t)m0 * N + n] = h0;
            *(__half2*)&outH[(size_t)(m0 + 8) * N + n] = h1;
        }
    }
}

// ---------------------------------------------------------------------------
// Tree attention: ONE WARP per token (b,l), all 8 heads, 16B loads.
// ---------------------------------------------------------------------------
__global__ __launch_bounds__(256) void tree_attn(
    const __half* __restrict__ qkv, const int* __restrict__ parents,
    __half* __restrict__ oh)
{
    int bl = blockIdx.x * 8 + (threadIdx.x >> 5);
    int lane = threadIdx.x & 31;
    int l = bl & (LL - 1);

    int p = parents[l];
    int pk = (p >= 0) ? (p + 1) : l;
    int pbl = (bl - l) + pk;

    size_t rb  = (size_t)bl  * NQKV + lane * 16;
    size_t prb = (size_t)pbl * NQKV + lane * 16;

    uint4 q0  = *(const uint4*)(qkv + rb);
    uint4 q1  = *(const uint4*)(qkv + rb + 8);
    uint4 k0  = *(const uint4*)(qkv + rb + 512);
    uint4 k1  = *(const uint4*)(qkv + rb + 520);
    uint4 kp0 = *(const uint4*)(qkv + prb + 512);
    uint4 kp1 = *(const uint4*)(qkv + prb + 520);

    float d0 = 0.0f, d1 = 0.0f;
    dot8(d0, q0, k0);  dot8(d0, q1, k1);
    dot8(d1, q0, kp0); dot8(d1, q1, kp1);

    // reduce within 4-lane head group
    #pragma unroll
    for (int off = 1; off < 4; off <<= 1) {
        d0 += __shfl_xor_sync(0xffffffffu, d0, off);
        d1 += __shfl_xor_sync(0xffffffffu, d1, off);
    }

    const float scale = 0.125f;   // 1/sqrt(64)
    float s0 = d0 * scale;
    float s1 = (p >= 0) ? d1 * scale : -1e9f;
    float m  = fmaxf(s0, s1);
    float e0 = __expf(s0 - m);
    float e1 = __expf(s1 - m);
    float inv = 1.0f / (e0 + e1);
    float a0 = e0 * inv, a1 = e1 * inv;

    uint4 v0  = *(const uint4*)(qkv + rb + 1024);
    uint4 v1  = *(const uint4*)(qkv + rb + 1032);
    uint4 vp0 = *(const uint4*)(qkv + prb + 1024);
    uint4 vp1 = *(const uint4*)(qkv + prb + 1032);

    uint4 o0, o1;
    {
        const __half2* vs = (const __half2*)&v0;
        const __half2* vp = (const __half2*)&vp0;
        __half2* oo = (__half2*)&o0;
        #pragma unroll
        for (int i = 0; i < 4; ++i) {
            float2 a = __half22float2(vs[i]);
            float2 b = __half22float2(vp[i]);
            __half2 r;
            r.x = __float2half_rn(a0 * a.x + a1 * b.x);
            r.y = __float2half_rn(a0 * a.y + a1 * b.y);
            oo[i] = r;
        }
        const __half2* vs1 = (const __half2*)&v1;
        const __half2* vp1h = (const __half2*)&vp1;
        __half2* oo1 = (__half2*)&o1;
        #pragma unroll
        for (int i = 0; i < 4; ++i) {
            float2 a = __half22float2(vs1[i]);
            float2 b = __half22float2(vp1h[i]);
            __half2 r;
            r.x = __float2half_rn(a0 * a.x + a1 * b.x);
            r.y = __float2half_rn(a0 * a.y + a1 * b.y);
            oo1[i] = r;
        }
    }

    size_t ob = (size_t)bl * DD + lane * 16;
    *(uint4*)(oh + ob)     = o0;
    *(uint4*)(oh + ob + 8) = o1;
}

// ---------------------------------------------------------------------------
// Fused residual-add + LayerNorm: ONE WARP per row, shfl-only, 16B loads.
// ---------------------------------------------------------------------------
__global__ __launch_bounds__(256) void add_ln(
    __half* __restrict__ h, const __half* __restrict__ r,
    const float* __restrict__ gamma, const float* __restrict__ beta)
{
    int row = blockIdx.x * 8 + (threadIdx.x >> 5);
    int lane = threadIdx.x & 31;
    size_t base = (size_t)row * DD + lane * 16;

    uint4 hv0 = *(const uint4*)(h + base);
    uint4 hv1 = *(const uint4*)(h + base + 8);
    uint4 rv0 = *(const uint4*)(r + base);
    uint4 rv1 = *(const uint4*)(r + base + 8);

    float x[16];
    {
        const __half2* hh0 = (const __half2*)&hv0;
        const __half2* hh1 = (const __half2*)&hv1;
        const __half2* rr0 = (const __half2*)&rv0;
        const __half2* rr1 = (const __half2*)&rv1;
        #pragma unroll
        for (int i = 0; i < 4; ++i) {
            float2 a = __half22float2(hh0[i]);
            float2 b = __half22float2(rr0[i]);
            x[2 * i]     = a.x + b.x;
            x[2 * i + 1] = a.y + b.y;
            float2 c = __half22float2(hh1[i]);
            float2 d = __half22float2(rr1[i]);
            x[8 + 2 * i]     = c.x + d.x;
            x[8 + 2 * i + 1] = c.y + d.y;
        }
    }

    float s = 0.0f, sq = 0.0f;
    #pragma unroll
    for (int i = 0; i < 16; ++i) { s += x[i]; sq += x[i] * x[i]; }
    #pragma unroll
    for (int off = 16; off; off >>= 1) {
        s  += __shfl_xor_sync(0xffffffffu, s, off);
        sq += __shfl_xor_sync(0xffffffffu, sq, off);
    }

    float mu = s * (1.0f / DD);
    float var = sq * (1.0f / DD) - mu * mu;
    float rstd = rsqrtf(var + 1e-6f);

    float4 g[4], b4[4];
    #pragma unroll
    for (int i = 0; i < 4; ++i) {
        g[i]  = *(const float4*)&gamma[lane * 16 + i * 4];
        b4[i] = *(const float4*)&beta[lane * 16 + i * 4];
    }

    uint4 o0, o1;
    __half2* oo0 = (__half2*)&o0;
    __half2* oo1 = (__half2*)&o1;
    #pragma unroll
    for (int i = 0; i < 2; ++i) {
        const float* gp = (const float*)&g[i];
        const float* bp = (const float*)&b4[i];
        #pragma unroll
        for (int j = 0; j < 2; ++j) {
            __half2 rr;
            rr.x = __float2half_rn((x[4 * i + 2 * j]     - mu) * rstd * gp[2 * j]     + bp[2 * j]);
            rr.y = __float2half_rn((x[4 * i + 2 * j + 1] - mu) * rstd * gp[2 * j + 1] + bp[2 * j + 1]);
            oo0[2 * i + j] = rr;
        }
    }
    #pragma unroll
    for (int i = 0; i < 2; ++i) {
        const float* gp = (const float*)&g[2 + i];
        const float* bp = (const float*)&b4[2 + i];
        #pragma unroll
        for (int j = 0; j < 2; ++j) {
            __half2 rr;
            rr.x = __float2half_rn((x[8 + 4 * i + 2 * j]     - mu) * rstd * gp[2 * j]     + bp[2 * j]);
            rr.y = __float2half_rn((x[8 + 4 * i + 2 * j + 1] - mu) * rstd * gp[2 * j + 1] + bp[2 * j + 1]);
            oo1[2 * i + j] = rr;
        }
    }

    *(uint4*)(h + base)     = o0;
    *(uint4*)(h + base + 8) = o1;
}

// ---------------------------------------------------------------------------
// Output head (V=21): one warp per row, Wout cached in SMEM, fp16 h input
// ---------------------------------------------------------------------------
__global__ __launch_bounds__(256) void out_proj(
    const __half* __restrict__ h, const float* __restrict__ Wout,
    const float* __restrict__ bout, float* __restrict__ out)
{
    __shared__ float sW[DD * VV];
    for (int i = threadIdx.x; i < DD * VV; i += 256) sW[i] = Wout[i];
    __syncthreads();

    int warp = threadIdx.x >> 5, lane = threadIdx.x & 31;
    int row = blockIdx.x * 8 + warp;
    const __half* hr = h + (size_t)row * DD;

    float acc = 0.0f;
    for (int d = 0; d < DD; d += 4) {
        float2 a = __half22float2(*(const __half2*)(hr + d));
        float2 b = __half22float2(*(const __half2*)(hr + d + 2));
        if (lane < VV) {
            acc += a.x * sW[(d + 0) * VV + lane];
            acc += a.y * sW[(d + 1) * VV + lane];
            acc += b.x * sW[(d + 2) * VV + lane];
            acc += b.y * sW[(d + 3) * VV + lane];
        }
    }
    if (lane < VV) out[(size_t)row * VV + lane] = acc + bout[lane];
}

// ---------------------------------------------------------------------------
// Host launcher
// ---------------------------------------------------------------------------
extern "C" void kernel_launch(void* const* d_in, const int* in_sizes, int n_in,
                              void* d_out, int out_size)
{
    const int*   x       = (const int*)  d_in[0];
    const int*   parents = (const int*)  d_in[1];
    const float* tok     = (const float*)d_in[2];
    const float* pos     = (const float*)d_in[3];
    const float* Wq      = (const float*)d_in[4];
    const float* bq      = (const float*)d_in[5];
    const float* Wk      = (const float*)d_in[6];
    const float* bk      = (const float*)d_in[7];
    const float* Wv      = (const float*)d_in[8];
    const float* bv      = (const float*)d_in[9];
    const float* Wo      = (const float*)d_in[10];
    const float* bo      = (const float*)d_in[11];
    const float* ln1_s   = (const float*)d_in[12];
    const float* ln1_b   = (const float*)d_in[13];
    const float* ln2_s   = (const float*)d_in[14];
    const float* ln2_b   = (const float*)d_in[15];
    const float* W1      = (const float*)d_in[16];
    const float* b1      = (const float*)d_in[17];
    const float* W2      = (const float*)d_in[18];
    const float* b2      = (const float*)d_in[19];
    const float* Wout    = (const float*)d_in[20];
    const float* bout    = (const float*)d_in[21];
    float* out = (float*)d_out;

    float *bqkv;
    __half *qkv, *tmp, *hin, *att, *ff, *w;
    cudaGetSymbolAddress((void**)&qkv,  g_qkv);
    cudaGetSymbolAddress((void**)&tmp,  g_tmp);
    cudaGetSymbolAddress((void**)&bqkv, g_bqkv);
    cudaGetSymbolAddress((void**)&hin,  g_hin);
    cudaGetSymbolAddress((void**)&att,  g_att);
    cudaGetSymbolAddress((void**)&ff,   g_ff);
    cudaGetSymbolAddress((void**)&w,    g_w);

    cudaFuncSetAttribute(gemm_tc, cudaFuncAttributeMaxDynamicSharedMemorySize, SMEM_GEMM);

    prep_weights<<<NLAYERS * 3072, 256>>>(Wq, Wk, Wv, Wo, W1, W2, w);
    prep_bias<<<NLAYERS * NQKV / 256, 256>>>(bq, bk, bv, bqkv);
    embed_kernel<<<(MM * DD / 4) / 256, 256>>>(x, tok, pos, hin);

    dim3 gQKV(NQKV / BN, MM / BM);   // 12 x 256
    dim3 gD(DD / BN, MM / BM);       // 4 x 256
    dim3 gF(FF / BN, MM / BM);       // 16 x 256

    for (int l = 0; l < NLAYERS; ++l) {
        size_t WB = (size_t)l * WPL;

        gemm_tc<<<gQKV, 256, SMEM_GEMM>>>(hin, w + WB + W_QKV, bqkv + (size_t)l * NQKV,
                                          qkv, MM, NQKV, DD, 0);

        tree_attn<<<MM / 8, 256>>>(qkv, parents, att);

        gemm_tc<<<gD, 256, SMEM_GEMM>>>(att, w + WB + W_O, bo + (size_t)l * DD,
                                        tmp, MM, DD, DD, 0);

        add_ln<<<MM / 8, 256>>>(hin, tmp, ln1_s + (size_t)l * DD, ln1_b + (size_t)l * DD);

        gemm_tc<<<gF, 256, SMEM_GEMM>>>(hin, w + WB + W_1, b1 + (size_t)l * FF,
                                        ff, MM, FF, DD, 1);

        gemm_tc<<<gD, 256, SMEM_GEMM>>>(ff, w + WB + W_2, b2 + (size_t)l * DD,
                                        tmp, MM, DD, FF, 0);

        add_ln<<<MM / 8, 256>>>(hin, tmp, ln2_s + (size_t)l * DD, ln2_b + (size_t)l * DD);
    }

    out_proj<<<MM / 8, 256>>>(hin, Wout, bout, out);
}